// round 2
// baseline (speedup 1.0000x reference)
#include <cuda_runtime.h>
#include <math.h>

#define Tn 4096
#define Hn 2048
#define En 32
#define Fn 768
#define TOPK 4

// ---------------- scratch (device globals, no allocation) ----------------
__device__ int   g_topk_idx[Tn * TOPK];
__device__ float g_topk_w[Tn * TOPK];
__device__ int   g_counts[En];
__device__ int   g_offsets[En];
__device__ int   g_cursor[En];
__device__ int   g_tok[Tn * TOPK];    // token id, grouped by expert
__device__ float g_tokw[Tn * TOPK];   // routing weight, grouped by expert
__device__ float g_hdn[(size_t)Tn * TOPK * Fn];  // ~50 MB intermediate

// ---------------- zero output + counters ----------------
__global__ void zero_kernel(float* out) {
    int n = Tn * Hn;
    for (int i = blockIdx.x * blockDim.x + threadIdx.x; i < n;
         i += gridDim.x * blockDim.x)
        out[i] = 0.f;
    if (blockIdx.x == 0 && threadIdx.x < En) {
        g_counts[threadIdx.x] = 0;
        g_cursor[threadIdx.x] = 0;
    }
}

// ---------------- router: logits, softmax, top-4, renorm ----------------
__global__ __launch_bounds__(256) void router_kernel(
    const float* __restrict__ x, const float* __restrict__ gw,
    float* __restrict__ logits_out)  // may be nullptr
{
    int t = blockIdx.x;
    int tid = threadIdx.x;
    int warp = tid >> 5, lane = tid & 31;

    __shared__ float sx[Hn];
    __shared__ float slog[En];

    for (int i = tid; i < Hn; i += 256) sx[i] = x[(size_t)t * Hn + i];
    __syncthreads();

    // 8 warps, each does 4 experts; coalesced weight reads
    for (int e = warp; e < En; e += 8) {
        const float* w = gw + (size_t)e * Hn;
        float acc = 0.f;
        for (int k = lane; k < Hn; k += 32) acc += sx[k] * w[k];
        #pragma unroll
        for (int o = 16; o > 0; o >>= 1)
            acc += __shfl_xor_sync(0xffffffffu, acc, o);
        if (lane == 0) slog[e] = acc;
    }
    __syncthreads();

    if (warp == 0) {
        float l = slog[lane];
        if (logits_out) logits_out[(size_t)t * En + lane] = l;

        // softmax (warp-wide, E=32)
        float m = l;
        #pragma unroll
        for (int o = 16; o > 0; o >>= 1)
            m = fmaxf(m, __shfl_xor_sync(0xffffffffu, m, o));
        float p = __expf(l - m);
        float s = p;
        #pragma unroll
        for (int o = 16; o > 0; o >>= 1)
            s += __shfl_xor_sync(0xffffffffu, s, o);
        p /= s;

        // top-4 via 4 argmax passes
        float myp = p;
        float tw[TOPK]; int ti[TOPK];
        float wsum = 0.f;
        #pragma unroll
        for (int j = 0; j < TOPK; j++) {
            float v = myp; int idx = lane;
            #pragma unroll
            for (int o = 16; o > 0; o >>= 1) {
                float ov = __shfl_xor_sync(0xffffffffu, v, o);
                int   oi = __shfl_xor_sync(0xffffffffu, idx, o);
                if (ov > v || (ov == v && oi < idx)) { v = ov; idx = oi; }
            }
            tw[j] = v; ti[j] = idx; wsum += v;
            if (lane == idx) myp = -1.f;
        }
        if (lane < TOPK) {
            int e = ti[lane];
            g_topk_idx[t * TOPK + lane] = e;
            g_topk_w[t * TOPK + lane] = tw[lane] / wsum;
            atomicAdd(&g_counts[e], 1);
        }
    }
}

// ---------------- exclusive scan over 32 expert counts ----------------
__global__ void scan_kernel() {
    int lane = threadIdx.x;
    int c = g_counts[lane];
    int inc = c;
    #pragma unroll
    for (int o = 1; o < 32; o <<= 1) {
        int nv = __shfl_up_sync(0xffffffffu, inc, o);
        if (lane >= o) inc += nv;
    }
    g_offsets[lane] = inc - c;
}

// ---------------- scatter token assignments into per-expert groups ----
__global__ void scatter_kernel() {
    int i = blockIdx.x * blockDim.x + threadIdx.x;
    if (i >= Tn * TOPK) return;
    int e = g_topk_idx[i];
    int pos = atomicAdd(&g_cursor[e], 1);
    int slot = g_offsets[e] + pos;
    g_tok[slot]  = i >> 2;
    g_tokw[slot] = g_topk_w[i];
}

// ---------------- GEMM1: hdn = w * silu(x@wg) * (x@wu), grouped ---------
__global__ __launch_bounds__(256) void gemmA_kernel(
    const float* __restrict__ x,
    const float* __restrict__ wg, const float* __restrict__ wu)
{
    int e = blockIdx.z;
    int cnt = g_counts[e];
    int m0 = blockIdx.y * 64;
    if (m0 >= cnt) return;
    int base = g_offsets[e];
    int n0 = blockIdx.x * 64;

    __shared__ float As[16][64];
    __shared__ float Bg[16][64];
    __shared__ float Bu[16][64];

    int tid = threadIdx.x;
    int tx = tid & 15, ty = tid >> 4;

    int am = tid >> 2;
    int ak = (tid & 3) * 4;
    int arow = m0 + am;
    int tokA = (arow < cnt) ? g_tok[base + arow] : -1;

    int bk = tid >> 4;
    int bn = (tid & 15) * 4;
    const float* wgp = wg + (size_t)e * Hn * Fn;
    const float* wup = wu + (size_t)e * Hn * Fn;

    float accg[4][4] = {}, accu[4][4] = {};

    for (int k0 = 0; k0 < Hn; k0 += 16) {
        float4 av = make_float4(0.f, 0.f, 0.f, 0.f);
        if (tokA >= 0)
            av = *(const float4*)(x + (size_t)tokA * Hn + k0 + ak);
        As[ak + 0][am] = av.x; As[ak + 1][am] = av.y;
        As[ak + 2][am] = av.z; As[ak + 3][am] = av.w;

        *(float4*)&Bg[bk][bn] =
            *(const float4*)(wgp + (size_t)(k0 + bk) * Fn + n0 + bn);
        *(float4*)&Bu[bk][bn] =
            *(const float4*)(wup + (size_t)(k0 + bk) * Fn + n0 + bn);
        __syncthreads();

        #pragma unroll
        for (int k = 0; k < 16; k++) {
            float4 a = *(const float4*)&As[k][ty * 4];
            float4 g = *(const float4*)&Bg[k][tx * 4];
            float4 u = *(const float4*)&Bu[k][tx * 4];
            float aa[4] = {a.x, a.y, a.z, a.w};
            float gg[4] = {g.x, g.y, g.z, g.w};
            float uu[4] = {u.x, u.y, u.z, u.w};
            #pragma unroll
            for (int i = 0; i < 4; i++)
                #pragma unroll
                for (int j = 0; j < 4; j++) {
                    accg[i][j] = fmaf(aa[i], gg[j], accg[i][j]);
                    accu[i][j] = fmaf(aa[i], uu[j], accu[i][j]);
                }
        }
        __syncthreads();
    }

    #pragma unroll
    for (int i = 0; i < 4; i++) {
        int row = m0 + ty * 4 + i;
        if (row >= cnt) continue;
        int slot = base + row;
        float w = g_tokw[slot];
        float* hp = g_hdn + (size_t)slot * Fn + n0 + tx * 4;
        #pragma unroll
        for (int j = 0; j < 4; j++) {
            float gv = accg[i][j];
            float sil = gv / (1.f + __expf(-gv));
            hp[j] = w * sil * accu[i][j];
        }
    }
}

// ---------------- GEMM2: out += hdn @ wd, grouped, atomic accumulate ----
__global__ __launch_bounds__(256) void gemmB_kernel(
    const float* __restrict__ wd, float* __restrict__ out)
{
    int e = blockIdx.z;
    int cnt = g_counts[e];
    int m0 = blockIdx.y * 64;
    if (m0 >= cnt) return;
    int base = g_offsets[e];
    int n0 = blockIdx.x * 64;

    __shared__ float As[16][64];
    __shared__ float Bs[16][64];

    int tid = threadIdx.x;
    int tx = tid & 15, ty = tid >> 4;

    int am = tid >> 2;
    int ak = (tid & 3) * 4;
    int arow = m0 + am;
    bool avalid = arow < cnt;
    size_t aslot = avalid ? (size_t)(base + arow) : 0;

    int bk = tid >> 4;
    int bn = (tid & 15) * 4;
    const float* wdp = wd + (size_t)e * Fn * Hn;

    float acc[4][4] = {};

    for (int k0 = 0; k0 < Fn; k0 += 16) {
        float4 av = make_float4(0.f, 0.f, 0.f, 0.f);
        if (avalid)
            av = *(const float4*)(g_hdn + aslot * Fn + k0 + ak);
        As[ak + 0][am] = av.x; As[ak + 1][am] = av.y;
        As[ak + 2][am] = av.z; As[ak + 3][am] = av.w;

        *(float4*)&Bs[bk][bn] =
            *(const float4*)(wdp + (size_t)(k0 + bk) * Hn + n0 + bn);
        __syncthreads();

        #pragma unroll
        for (int k = 0; k < 16; k++) {
            float4 a = *(const float4*)&As[k][ty * 4];
            float4 b = *(const float4*)&Bs[k][tx * 4];
            float aa[4] = {a.x, a.y, a.z, a.w};
            float bb[4] = {b.x, b.y, b.z, b.w};
            #pragma unroll
            for (int i = 0; i < 4; i++)
                #pragma unroll
                for (int j = 0; j < 4; j++)
                    acc[i][j] = fmaf(aa[i], bb[j], acc[i][j]);
        }
        __syncthreads();
    }

    #pragma unroll
    for (int i = 0; i < 4; i++) {
        int row = m0 + ty * 4 + i;
        if (row >= cnt) continue;
        int t = g_tok[base + row];
        float* op = out + (size_t)t * Hn + n0 + tx * 4;
        #pragma unroll
        for (int j = 0; j < 4; j++)
            atomicAdd(&op[j], acc[i][j]);
    }
}

// ---------------- launcher ----------------
extern "C" void kernel_launch(void* const* d_in, const int* in_sizes, int n_in,
                              void* d_out, int out_size) {
    const float* x  = (const float*)d_in[0];  // hidden_states [2,2048,2048]
    const float* gw = (const float*)d_in[1];  // gate_w [32,2048]
    const float* wg = (const float*)d_in[2];  // w_gate [32,2048,768]
    const float* wu = (const float*)d_in[3];  // w_up   [32,2048,768]
    const float* wd = (const float*)d_in[4];  // w_down [32,768,2048]
    float* out = (float*)d_out;

    // router logits go right after the main output if the buffer has room
    float* logits_out = nullptr;
    if (out_size >= Tn * Hn + Tn * En) logits_out = out + (size_t)Tn * Hn;

    zero_kernel<<<1024, 256>>>(out);
    router_kernel<<<Tn, 256>>>(x, gw, logits_out);
    scan_kernel<<<1, 32>>>();
    scatter_kernel<<<(Tn * TOPK + 255) / 256, 256>>>();
    gemmA_kernel<<<dim3(Fn / 64, Tn / 64, En), 256>>>(x, wg, wu);
    gemmB_kernel<<<dim3(Hn / 64, Tn / 64, En), 256>>>(wd, out);
}

// round 6
// speedup vs baseline: 1.3968x; 1.3968x over previous
#include <cuda_runtime.h>
#include <cuda_bf16.h>
#include <math.h>
#include <stdint.h>

#define Tn 4096
#define Hn 2048
#define En 32
#define Fn 768
#define TOPK 4
#define NSLOT (Tn * TOPK)

// ====================== asm helpers ======================
__device__ __forceinline__ uint32_t smem_u32(const void* p) {
    uint32_t a;
    asm("{ .reg .u64 t; cvta.to.shared.u64 t, %1; cvt.u32.u64 %0, t; }"
        : "=r"(a) : "l"(p));
    return a;
}

#define LDSM_X4(r0, r1, r2, r3, a) \
    asm volatile("ldmatrix.sync.aligned.m8n8.x4.shared.b16 {%0,%1,%2,%3}, [%4];" \
                 : "=r"(r0), "=r"(r1), "=r"(r2), "=r"(r3) : "r"(a))

#define MMA_BF16(d, a, b0, b1) \
    asm volatile("mma.sync.aligned.m16n8k16.row.col.f32.bf16.bf16.f32 " \
                 "{%0,%1,%2,%3}, {%4,%5,%6,%7}, {%8,%9}, {%0,%1,%2,%3};" \
                 : "+f"((d)[0]), "+f"((d)[1]), "+f"((d)[2]), "+f"((d)[3]) \
                 : "r"((a)[0]), "r"((a)[1]), "r"((a)[2]), "r"((a)[3]), \
                   "r"(b0), "r"(b1))

// ====================== device scratch (81 MB total) ======================
__device__ int   g_counts[En];
__device__ int   g_offsets[En];
__device__ int   g_cursor[En];
__device__ int   g_topk_idx[NSLOT];
__device__ float g_topk_w[NSLOT];
__device__ int   g_tok[NSLOT];
__device__ float g_tokw[NSLOT];

__device__ __align__(256) __nv_bfloat16 g_xhi[(size_t)Tn * Hn];     // 16 MB
__device__ __align__(256) __nv_bfloat16 g_xlo[(size_t)Tn * Hn];     // 16 MB
__device__ __align__(256) __nv_bfloat16 g_hdnhi[(size_t)NSLOT * Fn]; // 24 MB
__device__ __align__(256) __nv_bfloat16 g_hdnlo[(size_t)NSLOT * Fn]; // 24 MB

// ====================== small kernels ======================
__global__ void zero_kernel(float* out) {
    int n = Tn * Hn;
    for (int i = blockIdx.x * blockDim.x + threadIdx.x; i < n;
         i += gridDim.x * blockDim.x)
        out[i] = 0.f;
    if (blockIdx.x == 0 && threadIdx.x < En) {
        g_counts[threadIdx.x] = 0;
        g_cursor[threadIdx.x] = 0;
    }
}

__device__ __forceinline__ void split1(float f, __nv_bfloat16& h, __nv_bfloat16& l) {
    h = __float2bfloat16(f);
    l = __float2bfloat16(f - __bfloat162float(h));
}

__global__ __launch_bounds__(256) void convert_x_kernel(const float* __restrict__ x) {
    size_t i = ((size_t)blockIdx.x * 256 + threadIdx.x) * 4;
    float4 v = *(const float4*)(x + i);
    __nv_bfloat16 h0, l0, h1, l1, h2, l2, h3, l3;
    split1(v.x, h0, l0); split1(v.y, h1, l1);
    split1(v.z, h2, l2); split1(v.w, h3, l3);
    g_xhi[i] = h0; g_xhi[i+1] = h1; g_xhi[i+2] = h2; g_xhi[i+3] = h3;
    g_xlo[i] = l0; g_xlo[i+1] = l1; g_xlo[i+2] = l2; g_xlo[i+3] = l3;
}

// ====================== router / scan / scatter (proven in R1) ===========
__global__ __launch_bounds__(256) void router_kernel(
    const float* __restrict__ x, const float* __restrict__ gw,
    float* __restrict__ logits_out)
{
    int t = blockIdx.x, tid = threadIdx.x;
    int warp = tid >> 5, lane = tid & 31;
    __shared__ float sx[Hn];
    __shared__ float slog[En];
    for (int i = tid; i < Hn; i += 256) sx[i] = x[(size_t)t * Hn + i];
    __syncthreads();
    for (int e = warp; e < En; e += 8) {
        const float* w = gw + (size_t)e * Hn;
        float acc = 0.f;
        for (int k = lane; k < Hn; k += 32) acc += sx[k] * w[k];
        #pragma unroll
        for (int o = 16; o > 0; o >>= 1) acc += __shfl_xor_sync(~0u, acc, o);
        if (lane == 0) slog[e] = acc;
    }
    __syncthreads();
    if (warp == 0) {
        float l = slog[lane];
        if (logits_out) logits_out[(size_t)t * En + lane] = l;
        float m = l;
        #pragma unroll
        for (int o = 16; o > 0; o >>= 1) m = fmaxf(m, __shfl_xor_sync(~0u, m, o));
        float p = __expf(l - m), s = p;
        #pragma unroll
        for (int o = 16; o > 0; o >>= 1) s += __shfl_xor_sync(~0u, s, o);
        p /= s;
        float myp = p, tw[TOPK]; int ti[TOPK]; float wsum = 0.f;
        #pragma unroll
        for (int j = 0; j < TOPK; j++) {
            float v = myp; int idx = lane;
            #pragma unroll
            for (int o = 16; o > 0; o >>= 1) {
                float ov = __shfl_xor_sync(~0u, v, o);
                int   oi = __shfl_xor_sync(~0u, idx, o);
                if (ov > v || (ov == v && oi < idx)) { v = ov; idx = oi; }
            }
            tw[j] = v; ti[j] = idx; wsum += v;
            if (lane == idx) myp = -1.f;
        }
        if (lane < TOPK) {
            int e = ti[lane];
            g_topk_idx[t * TOPK + lane] = e;
            g_topk_w[t * TOPK + lane] = tw[lane] / wsum;
            atomicAdd(&g_counts[e], 1);
        }
    }
}

__global__ void scan_kernel() {
    int lane = threadIdx.x;
    int c = g_counts[lane], inc = c;
    #pragma unroll
    for (int o = 1; o < 32; o <<= 1) {
        int nv = __shfl_up_sync(~0u, inc, o);
        if (lane >= o) inc += nv;
    }
    g_offsets[lane] = inc - c;
}

__global__ void scatter_kernel() {
    int i = blockIdx.x * blockDim.x + threadIdx.x;
    if (i >= NSLOT) return;
    int e = g_topk_idx[i];
    int pos = atomicAdd(&g_cursor[e], 1);
    int slot = g_offsets[e] + pos;
    g_tok[slot]  = i >> 2;
    g_tokw[slot] = g_topk_w[i];
}

// ====================== GEMM1: 128x64 tile, BK=16, fused silu ============
__global__ __launch_bounds__(256) void gemm1_kernel(
    const float* __restrict__ wg, const float* __restrict__ wu)
{
    __shared__ __align__(16) __nv_bfloat16 sAh[128 * 16], sAl[128 * 16];
    __shared__ __align__(16) __nv_bfloat16 sGh[64 * 16], sGl[64 * 16];
    __shared__ __align__(16) __nv_bfloat16 sUh[64 * 16], sUl[64 * 16];
    __shared__ int stok[128];

    int e = blockIdx.z;
    int cnt = g_counts[e];
    int m0 = blockIdx.y * 128;
    if (m0 >= cnt) return;
    int base = g_offsets[e];
    int n0 = blockIdx.x * 64;
    int tid = threadIdx.x, wid = tid >> 5, lane = tid & 31;

    if (tid < 128) {
        int idx = base + m0 + tid;
        stok[tid] = g_tok[idx < NSLOT ? idx : NSLOT - 1];
    }
    __syncthreads();

    // A loads: 2 threads per row, 8 bf16 (16B) each
    int arow = tid >> 1, acb = (tid & 1) * 8;
    const __nv_bfloat16* pAh = g_xhi + (size_t)stok[arow] * Hn + acb;
    const __nv_bfloat16* pAl = g_xlo + (size_t)stok[arow] * Hn + acb;

    // B loads: fp32 from [K,N] weights, split + transpose into [N,K] smem
    int bk = tid >> 6;   // 0..3
    int bn = tid & 63;   // 0..63
    const float* pG = wg + (size_t)e * Hn * Fn + n0 + bn;
    const float* pU = wu + (size_t)e * Hn * Fn + n0 + bn;

    // ldmatrix offsets (row stride 32 B)
    int wm = wid & 1, wn = wid >> 1;
    uint32_t sAh_b = smem_u32(sAh), sAl_b = smem_u32(sAl);
    uint32_t sGh_b = smem_u32(sGh), sGl_b = smem_u32(sGl);
    uint32_t sUh_b = smem_u32(sUh), sUl_b = smem_u32(sUl);
    uint32_t aoff[4];
    {
        int r = wm * 64 + (lane & 15);
        uint32_t c = (uint32_t)(lane >> 4) * 16;
        #pragma unroll
        for (int mt = 0; mt < 4; mt++) aoff[mt] = (uint32_t)(r + mt * 16) * 32 + c;
    }
    uint32_t boff;
    {
        int r = wn * 16 + ((lane >> 4) << 3) + (lane & 7);
        boff = (uint32_t)r * 32 + (uint32_t)((lane >> 3) & 1) * 16;
    }

    float accG[4][2][4] = {}, accU[4][2][4] = {};

    for (int k0 = 0; k0 < Hn; k0 += 16) {
        // ---- stage A (hi/lo planes, already bf16) ----
        *(uint4*)(sAh + arow * 16 + acb) = *(const uint4*)(pAh + k0);
        *(uint4*)(sAl + arow * 16 + acb) = *(const uint4*)(pAl + k0);
        // ---- stage B: load fp32 [k][n], split, store transposed [n][k] ----
        #pragma unroll
        for (int kq = 0; kq < 4; kq++) {
            int k = kq * 4 + bk;
            float fg = pG[(size_t)(k0 + k) * Fn];
            float fu = pU[(size_t)(k0 + k) * Fn];
            __nv_bfloat16 h, l;
            split1(fg, h, l); sGh[bn * 16 + k] = h; sGl[bn * 16 + k] = l;
            split1(fu, h, l); sUh[bn * 16 + k] = h; sUl[bn * 16 + k] = l;
        }
        __syncthreads();

        uint32_t ah[4][4], al[4][4];
        #pragma unroll
        for (int mt = 0; mt < 4; mt++) {
            LDSM_X4(ah[mt][0], ah[mt][1], ah[mt][2], ah[mt][3], sAh_b + aoff[mt]);
            LDSM_X4(al[mt][0], al[mt][1], al[mt][2], al[mt][3], sAl_b + aoff[mt]);
        }
        uint32_t bgh[4], bgl[4], buh[4], bul[4];
        LDSM_X4(bgh[0], bgh[1], bgh[2], bgh[3], sGh_b + boff);
        LDSM_X4(bgl[0], bgl[1], bgl[2], bgl[3], sGl_b + boff);
        LDSM_X4(buh[0], buh[1], buh[2], buh[3], sUh_b + boff);
        LDSM_X4(bul[0], bul[1], bul[2], bul[3], sUl_b + boff);
        #pragma unroll
        for (int mt = 0; mt < 4; mt++) {
            #pragma unroll
            for (int nt = 0; nt < 2; nt++) {
                MMA_BF16(accG[mt][nt], ah[mt], bgh[nt * 2], bgh[nt * 2 + 1]);
                MMA_BF16(accG[mt][nt], ah[mt], bgl[nt * 2], bgl[nt * 2 + 1]);
                MMA_BF16(accG[mt][nt], al[mt], bgh[nt * 2], bgh[nt * 2 + 1]);
                MMA_BF16(accU[mt][nt], ah[mt], buh[nt * 2], buh[nt * 2 + 1]);
                MMA_BF16(accU[mt][nt], ah[mt], bul[nt * 2], bul[nt * 2 + 1]);
                MMA_BF16(accU[mt][nt], al[mt], buh[nt * 2], buh[nt * 2 + 1]);
            }
        }
        __syncthreads();
    }

    // ---- epilogue: h = w * silu(g) * u -> hdn hi/lo ----
    int r = lane >> 2, cp2 = (lane & 3) * 2;
    #pragma unroll
    for (int mt = 0; mt < 4; mt++) {
        #pragma unroll
        for (int half = 0; half < 2; half++) {
            int grow = m0 + wm * 64 + mt * 16 + r + half * 8;
            if (grow >= cnt) continue;
            int slot = base + grow;
            float wgt = g_tokw[slot];
            size_t ob = (size_t)slot * Fn + n0 + wn * 16 + cp2;
            #pragma unroll
            for (int nt = 0; nt < 2; nt++) {
                float g0 = accG[mt][nt][half * 2 + 0];
                float g1 = accG[mt][nt][half * 2 + 1];
                float u0 = accU[mt][nt][half * 2 + 0];
                float u1 = accU[mt][nt][half * 2 + 1];
                float h0 = wgt * (g0 / (1.f + __expf(-g0))) * u0;
                float h1 = wgt * (g1 / (1.f + __expf(-g1))) * u1;
                __nv_bfloat16 bh, bl;
                split1(h0, bh, bl);
                g_hdnhi[ob + nt * 8]     = bh;
                g_hdnlo[ob + nt * 8]     = bl;
                split1(h1, bh, bl);
                g_hdnhi[ob + nt * 8 + 1] = bh;
                g_hdnlo[ob + nt * 8 + 1] = bl;
            }
        }
    }
}

// ====================== GEMM2: 128x128 tile, BK=16, atomic out ===========
__global__ __launch_bounds__(256) void gemm2_kernel(
    const float* __restrict__ wd, float* __restrict__ out)
{
    __shared__ __align__(16) __nv_bfloat16 sAh[128 * 16], sAl[128 * 16];
    __shared__ __align__(16) __nv_bfloat16 sBh[128 * 16], sBl[128 * 16];

    int e = blockIdx.z;
    int cnt = g_counts[e];
    int m0 = blockIdx.y * 128;
    if (m0 >= cnt) return;
    int base = g_offsets[e];
    int n0 = blockIdx.x * 128;
    int tid = threadIdx.x, wid = tid >> 5, lane = tid & 31;

    int arow = tid >> 1, acb = (tid & 1) * 8;
    int sl = base + m0 + arow; if (sl >= NSLOT) sl = NSLOT - 1;
    const __nv_bfloat16* pAh = g_hdnhi + (size_t)sl * Fn + acb;
    const __nv_bfloat16* pAl = g_hdnlo + (size_t)sl * Fn + acb;

    int bk = tid >> 7;    // 0..1
    int bn = tid & 127;   // 0..127
    const float* pB = wd + (size_t)e * Fn * Hn + n0 + bn;

    int wm = wid & 1, wn = wid >> 1;
    uint32_t sAh_b = smem_u32(sAh), sAl_b = smem_u32(sAl);
    uint32_t sBh_b = smem_u32(sBh), sBl_b = smem_u32(sBl);
    uint32_t aoff[4];
    {
        int r = wm * 64 + (lane & 15);
        uint32_t c = (uint32_t)(lane >> 4) * 16;
        #pragma unroll
        for (int mt = 0; mt < 4; mt++) aoff[mt] = (uint32_t)(r + mt * 16) * 32 + c;
    }
    uint32_t boff[2];
    {
        int rb = ((lane >> 4) << 3) + (lane & 7);
        uint32_t c = (uint32_t)((lane >> 3) & 1) * 16;
        boff[0] = (uint32_t)(wn * 32 + rb) * 32 + c;
        boff[1] = (uint32_t)(wn * 32 + 16 + rb) * 32 + c;
    }

    float acc[4][4][4] = {};

    for (int k0 = 0; k0 < Fn; k0 += 16) {
        *(uint4*)(sAh + arow * 16 + acb) = *(const uint4*)(pAh + k0);
        *(uint4*)(sAl + arow * 16 + acb) = *(const uint4*)(pAl + k0);
        #pragma unroll
        for (int kq = 0; kq < 8; kq++) {
            int k = kq * 2 + bk;
            float f = pB[(size_t)(k0 + k) * Hn];
            __nv_bfloat16 h, l;
            split1(f, h, l);
            sBh[bn * 16 + k] = h;
            sBl[bn * 16 + k] = l;
        }
        __syncthreads();

        uint32_t ah[4][4], al[4][4];
        #pragma unroll
        for (int mt = 0; mt < 4; mt++) {
            LDSM_X4(ah[mt][0], ah[mt][1], ah[mt][2], ah[mt][3], sAh_b + aoff[mt]);
            LDSM_X4(al[mt][0], al[mt][1], al[mt][2], al[mt][3], sAl_b + aoff[mt]);
        }
        uint32_t bh[2][4], bl[2][4];
        #pragma unroll
        for (int p = 0; p < 2; p++) {
            LDSM_X4(bh[p][0], bh[p][1], bh[p][2], bh[p][3], sBh_b + boff[p]);
            LDSM_X4(bl[p][0], bl[p][1], bl[p][2], bl[p][3], sBl_b + boff[p]);
        }
        #pragma unroll
        for (int mt = 0; mt < 4; mt++) {
            #pragma unroll
            for (int nt = 0; nt < 4; nt++) {
                uint32_t* BH = &bh[nt >> 1][(nt & 1) * 2];
                uint32_t* BL = &bl[nt >> 1][(nt & 1) * 2];
                MMA_BF16(acc[mt][nt], ah[mt], BH[0], BH[1]);
                MMA_BF16(acc[mt][nt], ah[mt], BL[0], BL[1]);
                MMA_BF16(acc[mt][nt], al[mt], BH[0], BH[1]);
            }
        }
        __syncthreads();
    }

    // ---- epilogue: atomic accumulate into out ----
    int r = lane >> 2, cp2 = (lane & 3) * 2;
    #pragma unroll
    for (int mt = 0; mt < 4; mt++) {
        #pragma unroll
        for (int half = 0; half < 2; half++) {
            int grow = m0 + wm * 64 + mt * 16 + r + half * 8;
            if (grow >= cnt) continue;
            int tok = g_tok[base + grow];
            float* op = out + (size_t)tok * Hn + n0 + wn * 32 + cp2;
            #pragma unroll
            for (int nt = 0; nt < 4; nt++) {
                atomicAdd(&op[nt * 8],     acc[mt][nt][half * 2 + 0]);
                atomicAdd(&op[nt * 8 + 1], acc[mt][nt][half * 2 + 1]);
            }
        }
    }
}

// ====================== launcher ======================
extern "C" void kernel_launch(void* const* d_in, const int* in_sizes, int n_in,
                              void* d_out, int out_size) {
    const float* x  = (const float*)d_in[0];  // hidden_states
    const float* gw = (const float*)d_in[1];  // gate_w [E,H]
    const float* wg = (const float*)d_in[2];  // w_gate [E,H,F]
    const float* wu = (const float*)d_in[3];  // w_up   [E,H,F]
    const float* wd = (const float*)d_in[4];  // w_down [E,F,H]
    float* out = (float*)d_out;

    float* logits_out = nullptr;
    if (out_size >= Tn * Hn + Tn * En) logits_out = out + (size_t)Tn * Hn;

    zero_kernel<<<1024, 256>>>(out);
    convert_x_kernel<<<(Tn * Hn) / 1024, 256>>>(x);
    router_kernel<<<Tn, 256>>>(x, gw, logits_out);
    scan_kernel<<<1, 32>>>();
    scatter_kernel<<<(NSLOT + 255) / 256, 256>>>();
    gemm1_kernel<<<dim3(Fn / 64, NSLOT / 128, En), 256>>>(wg, wu);
    gemm2_kernel<<<dim3(Hn / 128, NSLOT / 128, En), 256>>>(wd, out);
}